// round 15
// baseline (speedup 1.0000x reference)
#include <cuda_runtime.h>

#define NN   3072
#define EE   3072
#define ELG  6144
#define FF   64
#define HH   4
#define RPH  768        // input rows per head after .view scramble
#define TABH 9437184    // 3072*3072, lg keys offset by this

// -------- scratch (__device__ globals; no allocations allowed) --------
__device__ float g_NV[NN * 256];            // layout [n][h*64+f]
__device__ float g_EV[EE * 256];            // layout [e][h*64+f]
__device__ float g_srkp[2 * 48 * 4 * 64];   // partial srk sums [g][chunk][h][f]
__device__ float g_WT[2 * 256 * 64];        // transposed Wq (node, edge)
__device__ float g_att4[2 * 3072 * 4];      // head-packed att [g][n][h]
__device__ float g_logit[8 * 3072];         // raw logits per (g,h)
__device__ float g_pmax[48];                // per-(gh,chunk) partial max
// counters, zeroed by cudaMemsetAsync each launch:
// [0..7]=softmax arrivals per gh, [8]=c_srk, [9]=c_wt, [10]=c_tab,
// [11]=c_gemm, [12]=c_att, [13]=c_win
__device__ int g_ctr[16];
__device__ unsigned char g_winN[EE];
__device__ unsigned char g_winL[ELG];
__device__ int g_tab[2 * TABH];             // dedup tournament table (zero invariant)

// packed f32x2 helpers (FFMA2 path — ptxas never emits this from plain C++)
__device__ __forceinline__ unsigned long long pk2(float w) {
    unsigned long long r;
    asm("mov.b64 %0, {%1, %1};" : "=l"(r) : "f"(w));
    return r;
}
__device__ __forceinline__ void ffma2(unsigned long long& d,
                                      unsigned long long a, unsigned long long b) {
    asm("fma.rn.f32x2 %0, %1, %2, %0;" : "+l"(d) : "l"(a), "l"(b));
}
__device__ __forceinline__ void unpk2(unsigned long long v, float& lo, float& hi) {
    asm("mov.b64 {%0, %1}, %2;" : "=f"(lo), "=f"(hi) : "l"(v));
}

__device__ __forceinline__ void spin_until(volatile int* ctr, int target) {
    // called by thread 0 only; acquire fence after
    while (*ctr != target) {}
    __threadfence();
}

// ============ kernel A: the whole pipeline, one launch ============
// roles by blockIdx.x (producers get lowest bids -> wave 1; 1184 = 2 waves @occ4):
//   [0,96)       srk partials (fused K projection)        -> ctr[8]
//   [96,104)     transpose Wq                              -> ctr[9]
//   [104,140)    dedup atomicMax tournament                -> ctr[10]
//   [140,524)    V gemms (NV 192, EV 192), permuted store  -> ctr[11]
//   [524,572)    workers (spin srk,wt): logits + last-block softmax -> ctr[12]
//   [572,608)    winner readers (spin tab)                 -> ctr[13]
//   [608,1184)   scatter blocks (spin gemm,att,win); first 36 also reset g_tab
__global__ void __launch_bounds__(256, 4) kA(
    const float* nin, const float* ein,
    const float* nkW, const float* nkb, const float* ekW, const float* ekb,
    const float* nvW, const float* nvb, const float* evW, const float* evb,
    const float* nqW, const float* eqW, const float* nqb, const float* eqb,
    const int* src, const int* dst, const int* lgs, const int* lgd,
    float* out)
{
    __shared__ __align__(16) float sm[8704];   // big staging union (34.8KB)
    __shared__ float s_srk[64];
    __shared__ __align__(16) float s_c[4 * 68];
    __shared__ float s_d[4];
    __shared__ float s_red[8];
    __shared__ float s_v;
    __shared__ int s_last;
    int b = blockIdx.x, tid = threadIdx.x;

    if (b < 96) {
        // ---- srk role: chunk of 64 nodes (16 KM rows per head) ----
        int g = b / 48, chunk = b % 48;
        const float* in = g ? ein : nin;
        const float* W  = g ? ekW : nkW;
        const float* bk = g ? ekb : nkb;
        float* s_in4 = sm;           // 4 heads * 16 rows * stride 68 = 4352
        float* s_wT  = sm + 4352;    // 4 * 68
        float* s_km  = sm + 4624;    // 4 * 64

        {   // vectorized fill
            const float4* in4g = (const float4*)in;
            int rr = tid >> 4, k4 = tid & 15;
            #pragma unroll
            for (int h2 = 0; h2 < 4; h2++)
                *(float4*)&s_in4[h2 * 1088 + rr * 68 + k4 * 4] =
                    in4g[(h2 * RPH + chunk * 16 + rr) * 16 + k4];
        }
        {   // transpose tiny K weights
            int k = tid >> 2, c = tid & 3;
            s_wT[c * 68 + k] = W[tid];
        }
        __syncthreads();
        int h = tid >> 6, idx = tid & 63;
        int rl = idx >> 2, c = idx & 3;
        float acc = bk[c];
        const float4* arow = (const float4*)&s_in4[h * 1088 + rl * 68];
        const float4* wrow = (const float4*)&s_wT[c * 68];
        #pragma unroll
        for (int k4 = 0; k4 < 16; k4++) {
            float4 a = arow[k4], w = wrow[k4];
            acc += a.x * w.x + a.y * w.y + a.z * w.z + a.w * w.w;
        }
        s_km[h * 64 + rl * 4 + c] = acc;
        __syncthreads();
        int f = tid & 63;
        float sacc = 0.f;
        int n0 = chunk * 64;
        #pragma unroll 8
        for (int nl = 0; nl < 64; nl++)
            sacc += in[(n0 + nl) * 64 + f] * s_km[h * 64 + nl];
        g_srkp[((g * 48 + chunk) * 4 + h) * 64 + f] = sacc;
        __threadfence();
        __syncthreads();
        if (tid == 0) atomicAdd(&g_ctr[8], 1);

    } else if (b < 104) {
        // ---- transpose Wq: [64k][256c] -> WT[256c][64k] ----
        int t = b - 96;
        int mat = t >> 2, tile = t & 3;
        const float* W = mat ? eqW : nqW;
        float* s = sm;
        #pragma unroll
        for (int i = 0; i < 16; i++) {
            int idx = i * 256 + tid;
            int k = idx >> 6, c = idx & 63;
            s[k * 65 + c] = W[k * 256 + tile * 64 + c];
        }
        __syncthreads();
        #pragma unroll
        for (int i = 0; i < 16; i++) {
            int idx = i * 256 + tid;
            int c = idx >> 6, k = idx & 63;
            g_WT[mat * 16384 + (tile * 64 + c) * 64 + k] = s[k * 65 + c];
        }
        __threadfence();
        __syncthreads();
        if (tid == 0) atomicAdd(&g_ctr[9], 1);

    } else if (b < 140) {
        // ---- dedup tournament: atomicMax(tab[key], e+1) ----
        int e = (b - 104) * 256 + tid;
        if (e < EE) {
            atomicMax(&g_tab[src[e] * 3072 + dst[e]], e + 1);
        } else {
            int l = e - EE;
            atomicMax(&g_tab[TABH + lgs[l] * 3072 + lgd[l]], l + 1);
        }
        __threadfence();
        __syncthreads();
        if (tid == 0) atomicAdd(&g_ctr[10], 1);

    } else if (b < 524) {
        // ---- V gemm role: [3072x64] @ [64x256] + bias, f32x2-packed ----
        // store permuted to [n][h*64+f] for contiguous per-edge gathers
        int i2 = b - 140;
        int mat = i2 / 192;
        int rem = i2 % 192;
        int r0 = (rem >> 2) * 64, c0 = (rem & 3) * 64;
        const float* in = mat ? ein : nin;
        const float* W  = mat ? evW : nvW;
        const float* bb = mat ? evb : nvb;
        float* outv     = mat ? g_EV : g_NV;
        float* As = sm;                  // 64 k * stride 68 = 4352
        float* Ws = sm + 4352;           // 64*64
        float* Bs = sm + 8448;           // 64

        #pragma unroll
        for (int i = 0; i < 16; i++) {   // A tile, transposed store (k-major)
            int idx = i * 256 + tid;
            int r = idx >> 6, k = idx & 63;
            As[k * 68 + r] = in[r0 * 64 + idx];
        }
        #pragma unroll
        for (int i = 0; i < 4; i++) {    // W tile, vectorized copy
            int idx = i * 256 + tid;
            int k = idx >> 4, c4 = idx & 15;
            *(float4*)&Ws[k * 64 + c4 * 4] =
                *(const float4*)&W[k * 256 + c0 + c4 * 4];
        }
        if (tid < 64) Bs[tid] = bb[c0 + tid];
        __syncthreads();

        int tx = tid & 15, ty = tid >> 4;
        int rl = ty * 4, cl = tx * 4;
        unsigned long long acc2[2][4];
        #pragma unroll
        for (int j = 0; j < 4; j++) {
            unsigned long long p = pk2(Bs[cl + j]);
            acc2[0][j] = p; acc2[1][j] = p;
        }

        #pragma unroll 16
        for (int k = 0; k < 64; k++) {
            ulonglong2 a = *(const ulonglong2*)&As[k * 68 + rl];
            float4 w = *(const float4*)&Ws[k * 64 + cl];
            unsigned long long wx = pk2(w.x), wy = pk2(w.y),
                               wz = pk2(w.z), ww = pk2(w.w);
            ffma2(acc2[0][0], a.x, wx); ffma2(acc2[1][0], a.y, wx);
            ffma2(acc2[0][1], a.x, wy); ffma2(acc2[1][1], a.y, wy);
            ffma2(acc2[0][2], a.x, wz); ffma2(acc2[1][2], a.y, wz);
            ffma2(acc2[0][3], a.x, ww); ffma2(acc2[1][3], a.y, ww);
        }
        // permuted store: GEMM (row, col) -> [nn][hB*64 + col%64]
        int hB = r0 / 768;
        int nnb = (r0 - hB * 768 + rl) * 4 + (c0 >> 6);
        #pragma unroll
        for (int p = 0; p < 2; p++) {
            float lo[4], hi[4];
            #pragma unroll
            for (int j = 0; j < 4; j++) unpk2(acc2[p][j], lo[j], hi[j]);
            *(float4*)&outv[(nnb + (2 * p)     * 4) * 256 + hB * 64 + cl] =
                make_float4(lo[0], lo[1], lo[2], lo[3]);
            *(float4*)&outv[(nnb + (2 * p + 1) * 4) * 256 + hB * 64 + cl] =
                make_float4(hi[0], hi[1], hi[2], hi[3]);
        }
        __threadfence();
        __syncthreads();
        if (tid == 0) atomicAdd(&g_ctr[11], 1);

    } else if (b < 572) {
        // ---- worker: (gh, chunk) logits + last-block softmax ----
        int w = b - 524;
        int gh = w / 6, chunk = w % 6;
        int g = gh >> 2, h = gh & 3;
        const float* in = g ? ein : nin;

        if (tid == 0) {
            spin_until(&g_ctr[8], 96);
            spin_until(&g_ctr[9], 8);
        }
        __syncthreads();

        // phase 1: reduce srk partials (48 chunks), scratch = sm
        {
            int f = tid & 63, p = tid >> 6;    // 4 groups x 12 chunks
            float a = 0.f;
            #pragma unroll
            for (int q = 0; q < 12; q++)
                a += g_srkp[((g * 48 + p * 12 + q) * 4 + h) * 64 + f];
            sm[tid] = a;
        }
        __syncthreads();
        if (tid < 64)
            s_srk[tid] = sm[tid] + sm[64 + tid] + sm[128 + tid] + sm[192 + tid];
        __syncthreads();

        // phase 2: c[j][k], d[j]
        {
            int j = tid & 3, k = tid >> 2;
            const float* wt = g_WT + g * 16384 + j * 4096;
            float a = 0.f;
            #pragma unroll 16
            for (int f = 0; f < 64; f++)
                a += wt[f * 64 + k] * s_srk[f];
            s_c[j * 68 + k] = a;
        }
        if (tid < 4) {
            const float* bq = g ? eqb : nqb;
            float dd = 0.f;
            #pragma unroll 16
            for (int f = 0; f < 64; f++) dd += bq[tid * 64 + f] * s_srk[f];
            s_d[tid] = dd;
        }
        __syncthreads();

        // phase 3: logits for this 128-row chunk (512 positions, 2/thread)
        {
            const float4* src4 =
                (const float4*)(in + (size_t)(h * RPH + chunk * 128) * 64);
            #pragma unroll
            for (int i = 0; i < 8; i++) {
                int idx = i * 256 + tid;
                int r = idx >> 4, k4 = idx & 15;
                *(float4*)&sm[r * 68 + k4 * 4] = src4[idx];
            }
        }
        __syncthreads();
        float lmax = -1e30f;
        #pragma unroll
        for (int it = 0; it < 2; it++) {
            int pos = it * 256 + tid;
            int ml = pos >> 2, jj = pos & 3;
            const float4* row = (const float4*)&sm[ml * 68];
            const float4* cj  = (const float4*)&s_c[jj * 68];
            float a0 = 0.f, a1 = 0.f, a2 = 0.f, a3 = 0.f;
            #pragma unroll
            for (int k = 0; k < 16; k += 4) {
                float4 r0 = row[k + 0], c0 = cj[k + 0];
                float4 r1 = row[k + 1], c1 = cj[k + 1];
                float4 r2 = row[k + 2], c2 = cj[k + 2];
                float4 r3 = row[k + 3], c3 = cj[k + 3];
                a0 += r0.x * c0.x + r0.y * c0.y + r0.z * c0.z + r0.w * c0.w;
                a1 += r1.x * c1.x + r1.y * c1.y + r1.z * c1.z + r1.w * c1.w;
                a2 += r2.x * c2.x + r2.y * c2.y + r2.z * c2.z + r2.w * c2.w;
                a3 += r3.x * c3.x + r3.y * c3.y + r3.z * c3.z + r3.w * c3.w;
            }
            float x = (s_d[jj] + ((a0 + a1) + (a2 + a3))) * 0.125f;
            g_logit[gh * 3072 + chunk * 512 + pos] = x;
            lmax = fmaxf(lmax, x);
        }
        #pragma unroll
        for (int o = 16; o > 0; o >>= 1)
            lmax = fmaxf(lmax, __shfl_xor_sync(0xffffffffu, lmax, o));
        if ((tid & 31) == 0) s_red[tid >> 5] = lmax;
        __syncthreads();
        if (tid == 0) {
            float m2 = s_red[0];
            #pragma unroll
            for (int i = 1; i < 8; i++) m2 = fmaxf(m2, s_red[i]);
            g_pmax[w] = m2;
        }
        __threadfence();
        __syncthreads();
        if (tid == 0) {
            int old = atomicAdd(&g_ctr[gh], 1);
            s_last = (old == 5);
        }
        __syncthreads();
        if (!s_last) return;
        __threadfence();

        // last arriver: softmax over all 3072 logits; head-packed att store
        float mx = -1e30f;
        #pragma unroll
        for (int c = 0; c < 6; c++) mx = fmaxf(mx, g_pmax[gh * 6 + c]);
        const float* lg = g_logit + gh * 3072;
        float* att4 = g_att4 + g * 3072 * 4 + h;
        float ev[12];
        float lsum = 0.f;
        #pragma unroll
        for (int i = 0; i < 12; i++) {
            ev[i] = __expf(lg[i * 256 + tid] - mx);
            lsum += ev[i];
        }
        #pragma unroll
        for (int o = 16; o > 0; o >>= 1)
            lsum += __shfl_xor_sync(0xffffffffu, lsum, o);
        if ((tid & 31) == 0) s_red[tid >> 5] = lsum;
        __syncthreads();
        if (tid == 0) {
            float s = 0.f;
            #pragma unroll
            for (int i = 0; i < 8; i++) s += s_red[i];
            s_v = 1.f / s;
        }
        __syncthreads();
        float inv = s_v;
        #pragma unroll
        for (int i = 0; i < 12; i++)
            att4[(i * 256 + tid) * 4] = ev[i] * inv;
        __threadfence();
        __syncthreads();
        if (tid == 0) atomicAdd(&g_ctr[12], 1);

    } else if (b < 608) {
        // ---- winner readers: spin on tab completion ----
        if (tid == 0) spin_until(&g_ctr[10], 36);
        __syncthreads();
        int idx = (b - 572) * 256 + tid;
        if (idx < EE) {
            g_winN[idx] = (g_tab[src[idx] * 3072 + dst[idx]] == idx + 1);
        } else {
            int l = idx - EE;
            g_winL[l] = (g_tab[TABH + lgs[l] * 3072 + lgd[l]] == l + 1);
        }
        __threadfence();
        __syncthreads();
        if (tid == 0) atomicAdd(&g_ctr[13], 1);

    } else {
        // ---- scatter blocks: spin on gemm/att/win, then message passing ----
        int w2 = b - 608;
        if (tid == 0) {
            spin_until(&g_ctr[13], 36);   // winners (implies tournament done)
            spin_until(&g_ctr[11], 384);  // V gemms
            spin_until(&g_ctr[12], 8);    // att
        }
        __syncthreads();

        // first 36 scatter blocks restore tournament-table zero invariant
        if (w2 < 36) {
            int e = w2 * 256 + tid;
            if (e < EE) g_tab[src[e] * 3072 + dst[e]] = 0;
            else {
                int l = e - EE;
                g_tab[TABH + lgs[l] * 3072 + lgd[l]] = 0;
            }
        }

        int u = tid >> 4;            // 16 edges per block
        int q = (tid & 15) * 4;      // float4 lane within feature dim
        if (w2 < 192) {                                    // node messages (edge att, g=1)
            int e = w2 * 16 + u;
            int s = src[e], d = dst[e];
            unsigned char win = g_winN[e];
            float4 at = *(const float4*)&g_att4[(3072 + e) * 4];
            float ar[4] = {at.x, at.y, at.z, at.w};
            float4 acc = make_float4(0.f, 0.f, 0.f, 0.f);
            #pragma unroll
            for (int h = 0; h < 4; h++) {
                float4 v = *(const float4*)&g_NV[d * 256 + h * 64 + q];
                acc.x += ar[h] * v.x; acc.y += ar[h] * v.y;
                acc.z += ar[h] * v.z; acc.w += ar[h] * v.w;
            }
            if (!win) return;
            acc.x *= 0.25f; acc.y *= 0.25f; acc.z *= 0.25f; acc.w *= 0.25f;
            atomicAdd((float4*)&out[s * 64 + q], acc);     // mean over heads
        } else {                                           // line-graph messages (node att, g=0)
            int l = (w2 - 192) * 16 + u;
            int e1 = lgs[l], e2 = lgd[l];
            int c = dst[e1];
            unsigned char win = g_winL[l];
            float4 at = *(const float4*)&g_att4[c * 4];
            float ar[4] = {at.x, at.y, at.z, at.w};
            float4 acc = make_float4(0.f, 0.f, 0.f, 0.f);
            #pragma unroll
            for (int h = 0; h < 4; h++) {
                float4 v = *(const float4*)&g_EV[e2 * 256 + h * 64 + q];
                acc.x += ar[h] * v.x; acc.y += ar[h] * v.y;
                acc.z += ar[h] * v.z; acc.w += ar[h] * v.w;
            }
            if (!win) return;
            acc.x *= 0.25f; acc.y *= 0.25f; acc.z *= 0.25f; acc.w *= 0.25f;
            atomicAdd((float4*)&out[NN * 64 + e1 * 64 + q], acc);
        }
    }
}

extern "C" void kernel_launch(void* const* d_in, const int* in_sizes, int n_in,
                              void* d_out, int out_size)
{
    const float* nin = (const float*)d_in[0];
    const float* ein = (const float*)d_in[1];
    const int* src = (const int*)d_in[2];
    const int* dst = (const int*)d_in[3];
    const int* lgs = (const int*)d_in[4];
    const int* lgd = (const int*)d_in[5];
    const float* nqW = (const float*)d_in[6];  const float* nqb = (const float*)d_in[7];
    const float* nkW = (const float*)d_in[8];  const float* nkb = (const float*)d_in[9];
    const float* nvW = (const float*)d_in[10]; const float* nvb = (const float*)d_in[11];
    const float* eqW = (const float*)d_in[12]; const float* eqb = (const float*)d_in[13];
    const float* ekW = (const float*)d_in[14]; const float* ekb = (const float*)d_in[15];
    const float* evW = (const float*)d_in[16]; const float* evb = (const float*)d_in[17];
    float* out = (float*)d_out;

    void* ctr_addr = nullptr;
    cudaGetSymbolAddress(&ctr_addr, g_ctr);
    cudaMemsetAsync(ctr_addr, 0, 16 * sizeof(int));
    cudaMemsetAsync(out, 0, (size_t)out_size * sizeof(float));

    kA<<<1184, 256>>>(nin, ein, nkW, nkb, ekW, ekb, nvW, nvb, evW, evb,
                      nqW, eqW, nqb, eqb, src, dst, lgs, lgd, out);
}

// round 16
// speedup vs baseline: 1.2197x; 1.2197x over previous
#include <cuda_runtime.h>

#define NN   3072
#define EE   3072
#define ELG  6144
#define FF   64
#define HH   4
#define RPH  768        // input rows per head after .view scramble
#define TABH 9437184    // 3072*3072, lg keys offset by this

// -------- scratch (__device__ globals; no allocations allowed) --------
__device__ float g_NV[NN * 256];            // layout [n][h*64+f]
__device__ float g_EV[EE * 256];            // layout [e][h*64+f]
__device__ float g_srkp[2 * 48 * 4 * 64];   // partial srk sums [g][chunk][h][f]
__device__ float g_WT[2 * 256 * 64];        // transposed Wq (node, edge)
__device__ float g_att4[2 * 3072 * 4];      // head-packed att [g][n][h]
__device__ float g_logit[8 * 3072];         // raw logits per (g,h)
__device__ float g_pmax[48];                // per-(gh,chunk) partial max
__device__ int   g_cnt[8];                  // softmax arrival counters (zero invariant)
__device__ int   c_srk, c_wt, c_tab;        // role-completion counters (zero invariant)
__device__ unsigned char g_winN[EE];
__device__ unsigned char g_winL[ELG];
__device__ int g_tab[2 * TABH];             // dedup tournament table (zero invariant)

// packed f32x2 helpers (FFMA2 path — ptxas never emits this from plain C++)
__device__ __forceinline__ unsigned long long pk2(float w) {
    unsigned long long r;
    asm("mov.b64 %0, {%1, %1};" : "=l"(r) : "f"(w));
    return r;
}
__device__ __forceinline__ void ffma2(unsigned long long& d,
                                      unsigned long long a, unsigned long long b) {
    asm("fma.rn.f32x2 %0, %1, %2, %0;" : "+l"(d) : "l"(a), "l"(b));
}
__device__ __forceinline__ void unpk2(unsigned long long v, float& lo, float& hi) {
    asm("mov.b64 {%0, %1}, %2;" : "=f"(lo), "=f"(hi) : "l"(v));
}

__device__ __forceinline__ void spin_until(volatile int* ctr, int target) {
    // called by thread 0 only; acquire fence after
    while (*ctr != target) {}
    __threadfence();
}

// ============ kernel A: everything except the final scatter ============
// roles by blockIdx.x (producers get lowest bids -> wave 1):
//   [0,96)      srk partials (fused K projection)        -> c_srk
//   [96,104)    transpose Wq                             -> c_wt
//   [104,140)   dedup atomicMax tournament               -> c_tab
//   [140,524)   V gemms: 64x64 tiles (NV 192, EV 192), permuted store
//   [524,572)   kBC workers (spin on c_srk,c_wt): logits + last-block softmax
//   [572,608)   winner readers: zero output, then (spin c_tab) read winners
__global__ void __launch_bounds__(256, 4) kA(
    const float* nin, const float* ein,
    const float* nkW, const float* nkb, const float* ekW, const float* ekb,
    const float* nvW, const float* nvb, const float* evW, const float* evb,
    const float* nqW, const float* eqW, const float* nqb, const float* eqb,
    const int* src, const int* dst, const int* lgs, const int* lgd,
    float* out)
{
    __shared__ __align__(16) float sm[8704];   // big staging union (34.8KB)
    __shared__ float s_srk[64];
    __shared__ __align__(16) float s_c[4 * 68];
    __shared__ float s_d[4];
    __shared__ float s_red[8];
    __shared__ float s_v;
    __shared__ int s_last;
    int b = blockIdx.x, tid = threadIdx.x;

    if (b < 96) {
        // ---- srk role: chunk of 64 nodes (16 KM rows per head) ----
        int g = b / 48, chunk = b % 48;
        const float* in = g ? ein : nin;
        const float* W  = g ? ekW : nkW;
        const float* bk = g ? ekb : nkb;
        float* s_in4 = sm;           // 4 heads * 16 rows * stride 68 = 4352
        float* s_wT  = sm + 4352;    // 4 * 68
        float* s_km  = sm + 4624;    // 4 * 64

        {   // vectorized fill
            const float4* in4g = (const float4*)in;
            int rr = tid >> 4, k4 = tid & 15;
            #pragma unroll
            for (int h2 = 0; h2 < 4; h2++)
                *(float4*)&s_in4[h2 * 1088 + rr * 68 + k4 * 4] =
                    in4g[(h2 * RPH + chunk * 16 + rr) * 16 + k4];
        }
        {   // transpose tiny K weights
            int k = tid >> 2, c = tid & 3;
            s_wT[c * 68 + k] = W[tid];
        }
        __syncthreads();
        int h = tid >> 6, idx = tid & 63;
        int rl = idx >> 2, c = idx & 3;
        float acc = bk[c];
        const float4* arow = (const float4*)&s_in4[h * 1088 + rl * 68];
        const float4* wrow = (const float4*)&s_wT[c * 68];
        #pragma unroll
        for (int k4 = 0; k4 < 16; k4++) {
            float4 a = arow[k4], w = wrow[k4];
            acc += a.x * w.x + a.y * w.y + a.z * w.z + a.w * w.w;
        }
        s_km[h * 64 + rl * 4 + c] = acc;
        __syncthreads();
        int f = tid & 63;
        float sacc = 0.f;
        int n0 = chunk * 64;
        #pragma unroll 8
        for (int nl = 0; nl < 64; nl++)
            sacc += in[(n0 + nl) * 64 + f] * s_km[h * 64 + nl];
        g_srkp[((g * 48 + chunk) * 4 + h) * 64 + f] = sacc;
        __threadfence();
        __syncthreads();
        if (tid == 0) atomicAdd(&c_srk, 1);

    } else if (b < 104) {
        // ---- transpose Wq: [64k][256c] -> WT[256c][64k] ----
        int t = b - 96;
        int mat = t >> 2, tile = t & 3;
        const float* W = mat ? eqW : nqW;
        float* s = sm;
        #pragma unroll
        for (int i = 0; i < 16; i++) {
            int idx = i * 256 + tid;
            int k = idx >> 6, c = idx & 63;
            s[k * 65 + c] = W[k * 256 + tile * 64 + c];
        }
        __syncthreads();
        #pragma unroll
        for (int i = 0; i < 16; i++) {
            int idx = i * 256 + tid;
            int c = idx >> 6, k = idx & 63;
            g_WT[mat * 16384 + (tile * 64 + c) * 64 + k] = s[k * 65 + c];
        }
        __threadfence();
        __syncthreads();
        if (tid == 0) atomicAdd(&c_wt, 1);

    } else if (b < 140) {
        // ---- dedup tournament: atomicMax(tab[key], e+1) ----
        int e = (b - 104) * 256 + tid;
        if (e < EE) {
            atomicMax(&g_tab[src[e] * 3072 + dst[e]], e + 1);
        } else {
            int l = e - EE;
            atomicMax(&g_tab[TABH + lgs[l] * 3072 + lgd[l]], l + 1);
        }
        __threadfence();
        __syncthreads();
        if (tid == 0) atomicAdd(&c_tab, 1);

    } else if (b < 524) {
        // ---- V gemm role: [3072x64] @ [64x256] + bias, f32x2-packed ----
        // store permuted to [n][h*64+f] for contiguous per-edge gathers in kD
        int i2 = b - 140;
        int mat = i2 / 192;
        int rem = i2 % 192;
        int r0 = (rem >> 2) * 64, c0 = (rem & 3) * 64;
        const float* in = mat ? ein : nin;
        const float* W  = mat ? evW : nvW;
        const float* bb = mat ? evb : nvb;
        float* outv     = mat ? g_EV : g_NV;
        float* As = sm;                  // 64 k * stride 68 = 4352
        float* Ws = sm + 4352;           // 64*64
        float* Bs = sm + 8448;           // 64

        #pragma unroll
        for (int i = 0; i < 16; i++) {   // A tile, transposed store (k-major)
            int idx = i * 256 + tid;
            int r = idx >> 6, k = idx & 63;
            As[k * 68 + r] = in[r0 * 64 + idx];
        }
        #pragma unroll
        for (int i = 0; i < 4; i++) {    // W tile, vectorized copy
            int idx = i * 256 + tid;
            int k = idx >> 4, c4 = idx & 15;
            *(float4*)&Ws[k * 64 + c4 * 4] =
                *(const float4*)&W[k * 256 + c0 + c4 * 4];
        }
        if (tid < 64) Bs[tid] = bb[c0 + tid];
        __syncthreads();

        int tx = tid & 15, ty = tid >> 4;
        int rl = ty * 4, cl = tx * 4;
        unsigned long long acc2[2][4];
        #pragma unroll
        for (int j = 0; j < 4; j++) {
            unsigned long long p = pk2(Bs[cl + j]);
            acc2[0][j] = p; acc2[1][j] = p;
        }

        #pragma unroll 16
        for (int k = 0; k < 64; k++) {
            ulonglong2 a = *(const ulonglong2*)&As[k * 68 + rl];
            float4 w = *(const float4*)&Ws[k * 64 + cl];
            unsigned long long wx = pk2(w.x), wy = pk2(w.y),
                               wz = pk2(w.z), ww = pk2(w.w);
            ffma2(acc2[0][0], a.x, wx); ffma2(acc2[1][0], a.y, wx);
            ffma2(acc2[0][1], a.x, wy); ffma2(acc2[1][1], a.y, wy);
            ffma2(acc2[0][2], a.x, wz); ffma2(acc2[1][2], a.y, wz);
            ffma2(acc2[0][3], a.x, ww); ffma2(acc2[1][3], a.y, ww);
        }
        // permuted store: GEMM (row, col) -> [nn][hB*64 + col%64]
        int hB = r0 / 768;
        int nnb = (r0 - hB * 768 + rl) * 4 + (c0 >> 6);
        #pragma unroll
        for (int p = 0; p < 2; p++) {
            float lo[4], hi[4];
            #pragma unroll
            for (int j = 0; j < 4; j++) unpk2(acc2[p][j], lo[j], hi[j]);
            *(float4*)&outv[(nnb + (2 * p)     * 4) * 256 + hB * 64 + cl] =
                make_float4(lo[0], lo[1], lo[2], lo[3]);
            *(float4*)&outv[(nnb + (2 * p + 1) * 4) * 256 + hB * 64 + cl] =
                make_float4(hi[0], hi[1], hi[2], hi[3]);
        }

    } else if (b < 572) {
        // ---- kBC worker: (gh, chunk) logits + last-block softmax ----
        int w = b - 524;
        int gh = w / 6, chunk = w % 6;
        int g = gh >> 2, h = gh & 3;
        const float* in = g ? ein : nin;

        if (tid == 0) {
            spin_until(&c_srk, 96);
            spin_until(&c_wt, 8);
        }
        __syncthreads();

        // phase 1: reduce srk partials (48 chunks), scratch = sm
        {
            int f = tid & 63, p = tid >> 6;    // 4 groups x 12 chunks
            float a = 0.f;
            #pragma unroll
            for (int q = 0; q < 12; q++)
                a += g_srkp[((g * 48 + p * 12 + q) * 4 + h) * 64 + f];
            sm[tid] = a;
        }
        __syncthreads();
        if (tid < 64)
            s_srk[tid] = sm[tid] + sm[64 + tid] + sm[128 + tid] + sm[192 + tid];
        __syncthreads();

        // phase 2: c[j][k], d[j]
        {
            int j = tid & 3, k = tid >> 2;
            const float* wt = g_WT + g * 16384 + j * 4096;
            float a = 0.f;
            #pragma unroll 16
            for (int f = 0; f < 64; f++)
                a += wt[f * 64 + k] * s_srk[f];
            s_c[j * 68 + k] = a;
        }
        if (tid < 4) {
            const float* bq = g ? eqb : nqb;
            float dd = 0.f;
            #pragma unroll 16
            for (int f = 0; f < 64; f++) dd += bq[tid * 64 + f] * s_srk[f];
            s_d[tid] = dd;
        }
        __syncthreads();

        // phase 3: logits for this 128-row chunk (512 positions, 2/thread)
        {
            const float4* src4 =
                (const float4*)(in + (size_t)(h * RPH + chunk * 128) * 64);
            #pragma unroll
            for (int i = 0; i < 8; i++) {
                int idx = i * 256 + tid;
                int r = idx >> 4, k4 = idx & 15;
                *(float4*)&sm[r * 68 + k4 * 4] = src4[idx];
            }
        }
        __syncthreads();
        float lmax = -1e30f;
        #pragma unroll
        for (int it = 0; it < 2; it++) {
            int pos = it * 256 + tid;
            int ml = pos >> 2, jj = pos & 3;
            const float4* row = (const float4*)&sm[ml * 68];
            const float4* cj  = (const float4*)&s_c[jj * 68];
            float a0 = 0.f, a1 = 0.f, a2 = 0.f, a3 = 0.f;
            #pragma unroll
            for (int k = 0; k < 16; k += 4) {
                float4 r0 = row[k + 0], c0 = cj[k + 0];
                float4 r1 = row[k + 1], c1 = cj[k + 1];
                float4 r2 = row[k + 2], c2 = cj[k + 2];
                float4 r3 = row[k + 3], c3 = cj[k + 3];
                a0 += r0.x * c0.x + r0.y * c0.y + r0.z * c0.z + r0.w * c0.w;
                a1 += r1.x * c1.x + r1.y * c1.y + r1.z * c1.z + r1.w * c1.w;
                a2 += r2.x * c2.x + r2.y * c2.y + r2.z * c2.z + r2.w * c2.w;
                a3 += r3.x * c3.x + r3.y * c3.y + r3.z * c3.z + r3.w * c3.w;
            }
            float x = (s_d[jj] + ((a0 + a1) + (a2 + a3))) * 0.125f;
            g_logit[gh * 3072 + chunk * 512 + pos] = x;
            lmax = fmaxf(lmax, x);
        }
        #pragma unroll
        for (int o = 16; o > 0; o >>= 1)
            lmax = fmaxf(lmax, __shfl_xor_sync(0xffffffffu, lmax, o));
        if ((tid & 31) == 0) s_red[tid >> 5] = lmax;
        __syncthreads();
        if (tid == 0) {
            float m2 = s_red[0];
            #pragma unroll
            for (int i = 1; i < 8; i++) m2 = fmaxf(m2, s_red[i]);
            g_pmax[w] = m2;
        }
        __threadfence();
        __syncthreads();
        if (tid == 0) {
            int old = atomicAdd(&g_cnt[gh], 1);
            s_last = (old == 5);
        }
        __syncthreads();
        if (!s_last) return;
        __threadfence();

        // last arriver: softmax over all 3072 logits; head-packed att store
        float mx = -1e30f;
        #pragma unroll
        for (int c = 0; c < 6; c++) mx = fmaxf(mx, g_pmax[gh * 6 + c]);
        const float* lg = g_logit + gh * 3072;
        float* att4 = g_att4 + g * 3072 * 4 + h;
        float ev[12];
        float lsum = 0.f;
        #pragma unroll
        for (int i = 0; i < 12; i++) {
            ev[i] = __expf(lg[i * 256 + tid] - mx);
            lsum += ev[i];
        }
        #pragma unroll
        for (int o = 16; o > 0; o >>= 1)
            lsum += __shfl_xor_sync(0xffffffffu, lsum, o);
        if ((tid & 31) == 0) s_red[tid >> 5] = lsum;
        __syncthreads();
        if (tid == 0) {
            float s = 0.f;
            #pragma unroll
            for (int i = 0; i < 8; i++) s += s_red[i];
            s_v = 1.f / s;
            g_cnt[gh] = 0;             // restore counter invariant
        }
        __syncthreads();
        float inv = s_v;
        #pragma unroll
        for (int i = 0; i < 12; i++)
            att4[(i * 256 + tid) * 4] = ev[i] * inv;

    } else {
        // ---- winner readers: zero output first, then spin + read winners ----
        int w = b - 572;   // 0..35
        {   // zero output: 98304 float4 over 9216 threads = 11 each (guarded)
            float4* o4 = (float4*)out;
            int base = w * 256 + tid;
            #pragma unroll
            for (int i = 0; i < 11; i++) {
                int idx = base + i * 9216;
                if (idx < 98304) o4[idx] = make_float4(0.f, 0.f, 0.f, 0.f);
            }
        }
        if (tid == 0) spin_until(&c_tab, 36);
        __syncthreads();
        int idx = w * 256 + tid;
        if (idx < EE) {
            g_winN[idx] = (g_tab[src[idx] * 3072 + dst[idx]] == idx + 1);
        } else {
            int l = idx - EE;
            g_winL[l] = (g_tab[TABH + lgs[l] * 3072 + lgd[l]] == l + 1);
        }
    }
}

// ======= kernel D: warp-per-edge scatter (32 lanes, float2 atomics) =======
// blocks 0-35 also reset the tournament table; block 36 resets role counters
__global__ void __launch_bounds__(256) kD(
    const int* src, const int* dst, const int* lgs, const int* lgd, float* out)
{
    int tid = threadIdx.x;
    int bx = blockIdx.x;

    if (bx < 36) {
        int e = bx * 256 + tid;
        if (e < EE) g_tab[src[e] * 3072 + dst[e]] = 0;
        else {
            int l = e - EE;
            g_tab[TABH + lgs[l] * 3072 + lgd[l]] = 0;
        }
    } else if (bx == 36 && tid < 3) {
        if (tid == 0) c_srk = 0;
        else if (tid == 1) c_wt = 0;
        else c_tab = 0;
    }

    int wid = bx * 8 + (tid >> 5);   // global warp id == edge index
    int lane = tid & 31;
    int q = lane * 2;                // float2 lane within feature dim

    if (wid < EE) {                                    // node messages (edge att, g=1)
        int e = wid;
        int s = src[e], d = dst[e];
        unsigned char win = g_winN[e];
        float4 at = *(const float4*)&g_att4[(3072 + e) * 4];
        float ar[4] = {at.x, at.y, at.z, at.w};
        float2 acc = make_float2(0.f, 0.f);
        #pragma unroll
        for (int h = 0; h < 4; h++) {
            float2 v = *(const float2*)&g_NV[d * 256 + h * 64 + q];
            acc.x += ar[h] * v.x; acc.y += ar[h] * v.y;
        }
        if (!win) return;
        acc.x *= 0.25f; acc.y *= 0.25f;
        atomicAdd((float2*)&out[s * 64 + q], acc);     // mean over heads
    } else {                                           // line-graph messages (node att, g=0)
        int l = wid - EE;
        int e1 = lgs[l], e2 = lgd[l];
        int c = dst[e1];
        unsigned char win = g_winL[l];
        float4 at = *(const float4*)&g_att4[c * 4];
        float ar[4] = {at.x, at.y, at.z, at.w};
        float2 acc = make_float2(0.f, 0.f);
        #pragma unroll
        for (int h = 0; h < 4; h++) {
            float2 v = *(const float2*)&g_EV[e2 * 256 + h * 64 + q];
            acc.x += ar[h] * v.x; acc.y += ar[h] * v.y;
        }
        if (!win) return;
        acc.x *= 0.25f; acc.y *= 0.25f;
        atomicAdd((float2*)&out[NN * 64 + e1 * 64 + q], acc);
    }
}

extern "C" void kernel_launch(void* const* d_in, const int* in_sizes, int n_in,
                              void* d_out, int out_size)
{
    const float* nin = (const float*)d_in[0];
    const float* ein = (const float*)d_in[1];
    const int* src = (const int*)d_in[2];
    const int* dst = (const int*)d_in[3];
    const int* lgs = (const int*)d_in[4];
    const int* lgd = (const int*)d_in[5];
    const float* nqW = (const float*)d_in[6];  const float* nqb = (const float*)d_in[7];
    const float* nkW = (const float*)d_in[8];  const float* nkb = (const float*)d_in[9];
    const float* nvW = (const float*)d_in[10]; const float* nvb = (const float*)d_in[11];
    const float* eqW = (const float*)d_in[12]; const float* eqb = (const float*)d_in[13];
    const float* ekW = (const float*)d_in[14]; const float* ekb = (const float*)d_in[15];
    const float* evW = (const float*)d_in[16]; const float* evb = (const float*)d_in[17];
    float* out = (float*)d_out;

    kA<<<608, 256>>>(nin, ein, nkW, nkb, ekW, ekb, nvW, nvb, evW, evb,
                     nqW, eqW, nqb, eqb, src, dst, lgs, lgd, out);
    kD<<<1152, 256>>>(src, dst, lgs, lgd, out);
}